// round 16
// baseline (speedup 1.0000x reference)
#include <cuda_runtime.h>
#include <cfloat>

#define BATCH 4
#define M 4096
#define TX 128
#define NW (TX / 32)            // 4 warps
#define R 4                     // x-points per thread (2 packed pairs)
#define XPB (TX * R)            // 512 x per block
#define XT (M / XPB)            // 8 x-tiles
#define YC 32                   // y-chunks
#define YCHUNK (M / YC)         // 128 y per chunk
#define NBLK (BATCH * XT * YC)  // 1024 blocks

typedef unsigned long long ull;

// Blackwell packed f32x2 (PTX 8.6+, sm_100+): fma/add only — no packed min.
#define FMA2(d, a, b, c) \
    asm("fma.rn.f32x2 %0, %1, %2, %3;" : "=l"(d) : "l"(a), "l"(b), "l"(c))
#define ADD2(d, a, b) \
    asm("add.rn.f32x2 %0, %1, %2;" : "=l"(d) : "l"(a), "l"(b))
#define PACK2(d, lo, hi) \
    asm("mov.b64 %0, {%1, %2};" : "=l"(d) : "f"(lo), "f"(hi))
#define UNPACK2(lo, hi, d) \
    asm("mov.b64 {%0, %1}, %2;" : "=f"(lo), "=f"(hi) : "l"(d))

// Order-preserving min-keys: key = ~float_bits(d^2), d^2 >= 0.
// Larger key == smaller d^2; all real keys > 0, so zero-init is the identity
// for atomicMax. chamfer_reduce resets entries to 0 after consuming them,
// so every graph replay starts from the identity state.
__device__ unsigned int g_rowkey[BATCH * M];  // [b][x]  min over all y
__device__ unsigned int g_colkey[BATCH * M];  // [b][y]  min over all x

__global__ __launch_bounds__(TX) void chamfer_main(const float* __restrict__ x,
                                                   const float* __restrict__ y) {
    // y points stored pre-duplicated for packed FMA: slot j holds
    // {py0,py0}{py1,py1}{py2,py2}{|p|^2,|p|^2} = 32 bytes. Doubled so
    // slot lane+k needs no mask.
    __shared__ ulonglong2 syd[2 * YCHUNK][2];
    __shared__ float scol[NW][2 * YCHUNK];   // per-warp col-min partials

    int bid = blockIdx.x;
    int yc = bid & (YC - 1);
    int xt = (bid >> 5) & (XT - 1);
    int b  = bid >> 8;

    int tid = threadIdx.x;
    int lane = tid & 31;
    int w = tid >> 5;

    // load y chunk, precompute |p|^2, store duplicated halves
    const float* ysrc = y + ((size_t)b * M + yc * YCHUNK) * 3;
    if (tid < YCHUNK) {
        float p0 = ysrc[tid * 3 + 0];
        float p1 = ysrc[tid * 3 + 1];
        float p2 = ysrc[tid * 3 + 2];
        float pw = fmaf(p0, p0, fmaf(p1, p1, p2 * p2));
        ull u0, u1, u2, u3;
        PACK2(u0, p0, p0);
        PACK2(u1, p1, p1);
        PACK2(u2, p2, p2);
        PACK2(u3, pw, pw);
        ulonglong2 A = make_ulonglong2(u0, u1);
        ulonglong2 B = make_ulonglong2(u2, u3);
        syd[tid][0] = A; syd[tid][1] = B;
        syd[tid + YCHUNK][0] = A; syd[tid + YCHUNK][1] = B;
    }
#pragma unroll
    for (int i = 0; i < NW * 2 * YCHUNK / TX; i++)
        ((float*)scol)[i * TX + tid] = FLT_MAX;

    // my R x-points -> packed pair constants (pair q = x_{2q}, x_{2q+1})
    ull n0[2], n1[2], n2[2], sx2[2];
    float rmin[R];
    const float* xsrc = x + ((size_t)b * M + xt * XPB) * 3;
#pragma unroll
    for (int q = 0; q < 2; q++) {
        float a0[2], a1[2], a2[2], sx[2];
#pragma unroll
        for (int h = 0; h < 2; h++) {
            int xi = tid + (2 * q + h) * TX;
            a0[h] = xsrc[xi * 3 + 0];
            a1[h] = xsrc[xi * 3 + 1];
            a2[h] = xsrc[xi * 3 + 2];
            sx[h] = fmaf(a0[h], a0[h], fmaf(a1[h], a1[h], a2[h] * a2[h]));
            rmin[2 * q + h] = FLT_MAX;
        }
        float m00 = -2.0f * a0[0], m01 = -2.0f * a0[1];
        float m10 = -2.0f * a1[0], m11 = -2.0f * a1[1];
        float m20 = -2.0f * a2[0], m21 = -2.0f * a2[1];
        PACK2(n0[q], m00, m01);
        PACK2(n1[q], m10, m11);
        PACK2(n2[q], m20, m21);
        PACK2(sx2[q], sx[0], sx[1]);
    }
    __syncthreads();

    // volatile pins LDS/STS order: lane-staggered linear index gives distinct
    // addresses within each step; a slot written by lane l+1 at step k is
    // re-read by lane l at step k+1 — same warp, program order through LSU.
    volatile float* sc = scol[w] + lane;
    const ulonglong2* syp = &syd[lane][0];

#pragma unroll 8
    for (int k = 0; k < YCHUNK; k++) {
        ulonglong2 A = syp[2 * k];       // {py0,py0} {py1,py1}
        ulonglong2 B = syp[2 * k + 1];   // {py2,py2} {pw,pw}
        ull t0, t1, d01, d23;
        FMA2(t0, n2[0], B.x, B.y);
        FMA2(t0, n1[0], A.y, t0);
        FMA2(t0, n0[0], A.x, t0);
        ADD2(d01, t0, sx2[0]);
        FMA2(t1, n2[1], B.x, B.y);
        FMA2(t1, n1[1], A.y, t1);
        FMA2(t1, n0[1], A.x, t1);
        ADD2(d23, t1, sx2[1]);
        float d0, d1, d2, d3;
        UNPACK2(d0, d1, d01);
        UNPACK2(d2, d3, d23);
        rmin[0] = fminf(rmin[0], d0);
        rmin[1] = fminf(rmin[1], d1);
        rmin[2] = fminf(rmin[2], d2);
        rmin[3] = fminf(rmin[3], d3);
        float c = fminf(fminf(d0, d1), fminf(d2, d3));
        sc[k] = fminf(sc[k], c);
    }

    // rows: fold via order-preserving atomicMax key
#pragma unroll
    for (int r = 0; r < R; r++) {
        unsigned int key = ~__float_as_uint(fmaxf(rmin[r], 0.0f));
        atomicMax(&g_rowkey[(size_t)b * M + xt * XPB + tid + r * TX], key);
    }

    __syncthreads();

    // merge doubled halves + warps, fold cols via atomicMax key
    if (tid < YCHUNK) {
        float v = FLT_MAX;
#pragma unroll
        for (int i = 0; i < NW; i++)
            v = fminf(v, fminf(scol[i][tid], scol[i][tid + YCHUNK]));
        unsigned int key = ~__float_as_uint(fmaxf(v, 0.0f));
        atomicMax(&g_colkey[(size_t)b * M + yc * YCHUNK + tid], key);
    }
}

// 4 blocks, one per batch. PDL secondary: scheduled while chamfer_main's
// tail wave still runs, executes on main's completion. Reads 4096 row +
// 4096 col keys as uint4 (coalesced), sqrt-sums, resets keys to 0, writes
// out[b] directly. Deterministic: fixed accumulation and reduction order.
__global__ __launch_bounds__(256) void chamfer_reduce(float* __restrict__ out) {
    cudaGridDependencySynchronize();

    int b   = blockIdx.x;
    int tid = threadIdx.x;
    float sum = 0.0f;

    uint4* rbase = (uint4*)(g_rowkey + (size_t)b * M);
    uint4* cbase = (uint4*)(g_colkey + (size_t)b * M);
    const uint4 zero4 = make_uint4(0u, 0u, 0u, 0u);

#pragma unroll
    for (int r = 0; r < M / 4 / 256; r++) {   // 4 iterations
        uint4 kr = rbase[r * 256 + tid];
        rbase[r * 256 + tid] = zero4;
        sum += sqrtf(__uint_as_float(~kr.x)) + sqrtf(__uint_as_float(~kr.y)) +
               sqrtf(__uint_as_float(~kr.z)) + sqrtf(__uint_as_float(~kr.w));
        uint4 kc = cbase[r * 256 + tid];
        cbase[r * 256 + tid] = zero4;
        sum += sqrtf(__uint_as_float(~kc.x)) + sqrtf(__uint_as_float(~kc.y)) +
               sqrtf(__uint_as_float(~kc.z)) + sqrtf(__uint_as_float(~kc.w));
    }

    __shared__ float red[8];
    for (int o = 16; o; o >>= 1) sum += __shfl_down_sync(0xffffffffu, sum, o);
    if ((tid & 31) == 0) red[tid >> 5] = sum;
    __syncthreads();
    if (tid == 0) {
        float s = 0.0f;
#pragma unroll
        for (int i = 0; i < 8; i++) s += red[i];
        out[b] = s * (1.0f / (float)M);
    }
}

extern "C" void kernel_launch(void* const* d_in, const int* in_sizes, int n_in,
                              void* d_out, int out_size) {
    const float* x = (const float*)d_in[0];
    const float* y = (const float*)d_in[1];
    float* out = (float*)d_out;

    chamfer_main<<<NBLK, TX>>>(x, y);

    cudaLaunchConfig_t cfg = {};
    cfg.gridDim = dim3(BATCH, 1, 1);
    cfg.blockDim = dim3(256, 1, 1);
    cfg.dynamicSmemBytes = 0;
    cfg.stream = 0;
    cudaLaunchAttribute attr[1];
    attr[0].id = cudaLaunchAttributeProgrammaticStreamSerialization;
    attr[0].val.programmaticStreamSerializationAllowed = 1;
    cfg.attrs = attr;
    cfg.numAttrs = 1;
    cudaLaunchKernelEx(&cfg, chamfer_reduce, out);
}

// round 17
// speedup vs baseline: 1.6903x; 1.6903x over previous
#include <cuda_runtime.h>
#include <cfloat>

#define BATCH 4
#define M 4096
#define TX 128
#define NW (TX / 32)            // 4 warps
#define R 4                     // x-points per thread
#define XPB (TX * R)            // 512 x per block
#define XT (M / XPB)            // 8 x-tiles
#define YC 32                   // y-chunks
#define YCHUNK (M / YC)         // 128 y per chunk
#define NBLK (BATCH * XT * YC)  // 1024 blocks

// Order-preserving min-keys: key = ~float_bits(d^2), d^2 >= 0.
// Larger key == smaller d^2; all real keys > 0, so zero-init is the identity
// for atomicMax. chamfer_reduce resets entries to 0 after consuming them,
// so every graph replay starts from the identity state.
__device__ unsigned int g_rowkey[BATCH * M];  // [b][x]  min over all y
__device__ unsigned int g_colkey[BATCH * M];  // [b][y]  min over all x

__global__ __launch_bounds__(TX) void chamfer_main(const float* __restrict__ x,
                                                   const float* __restrict__ y) {
    __shared__ float4 sy[2 * YCHUNK];        // y chunk doubled: linear index
    __shared__ float scol[NW][2 * YCHUNK];   // per-warp col-min, doubled

    int bid = blockIdx.x;
    int yc = bid & (YC - 1);
    int xt = (bid >> 5) & (XT - 1);
    int b  = bid >> 8;

    int tid = threadIdx.x;
    int lane = tid & 31;
    int w = tid >> 5;

    // load y chunk (duplicated so sy[lane+k] needs no mask), precompute |p|^2
    const float* ysrc = y + ((size_t)b * M + yc * YCHUNK) * 3;
    if (tid < YCHUNK) {
        float p0 = ysrc[tid * 3 + 0];
        float p1 = ysrc[tid * 3 + 1];
        float p2 = ysrc[tid * 3 + 2];
        float4 v = make_float4(p0, p1, p2, fmaf(p0, p0, fmaf(p1, p1, p2 * p2)));
        sy[tid] = v;
        sy[tid + YCHUNK] = v;
    }
#pragma unroll
    for (int i = 0; i < NW * 2 * YCHUNK / TX; i++)
        ((float*)scol)[i * TX + tid] = FLT_MAX;

    // my R x-points -> registers
    float n0[R], n1[R], n2[R], sx[R], rmin[R];
    const float* xsrc = x + ((size_t)b * M + xt * XPB) * 3;
#pragma unroll
    for (int r = 0; r < R; r++) {
        int xi = tid + r * TX;
        float a0 = xsrc[xi * 3 + 0];
        float a1 = xsrc[xi * 3 + 1];
        float a2 = xsrc[xi * 3 + 2];
        sx[r] = fmaf(a0, a0, fmaf(a1, a1, a2 * a2));
        n0[r] = -2.0f * a0;
        n1[r] = -2.0f * a1;
        n2[r] = -2.0f * a2;
        rmin[r] = FLT_MAX;
    }
    __syncthreads();

    // volatile pins LDS/STS order: lane-staggered linear index gives distinct
    // addresses within each step; an address written by lane l+1 at step k is
    // re-read by lane l at step k+1 — same warp, program order through LSU.
    volatile float* sc = scol[w] + lane;
    const float4* syp = sy + lane;

#pragma unroll 8
    for (int k = 0; k < YCHUNK; k++) {
        float4 p = syp[k];
        float d0 = sx[0] + fmaf(n0[0], p.x, fmaf(n1[0], p.y, fmaf(n2[0], p.z, p.w)));
        float d1 = sx[1] + fmaf(n0[1], p.x, fmaf(n1[1], p.y, fmaf(n2[1], p.z, p.w)));
        float d2 = sx[2] + fmaf(n0[2], p.x, fmaf(n1[2], p.y, fmaf(n2[2], p.z, p.w)));
        float d3 = sx[3] + fmaf(n0[3], p.x, fmaf(n1[3], p.y, fmaf(n2[3], p.z, p.w)));
        rmin[0] = fminf(rmin[0], d0);
        rmin[1] = fminf(rmin[1], d1);
        rmin[2] = fminf(rmin[2], d2);
        rmin[3] = fminf(rmin[3], d3);
        float c = fminf(fminf(d0, d1), fminf(d2, d3));
        sc[k] = fminf(sc[k], c);
    }

    // rows: fold via order-preserving atomicMax key
#pragma unroll
    for (int r = 0; r < R; r++) {
        unsigned int key = ~__float_as_uint(fmaxf(rmin[r], 0.0f));
        atomicMax(&g_rowkey[(size_t)b * M + xt * XPB + tid + r * TX], key);
    }

    __syncthreads();

    // merge doubled halves + warps, fold cols via atomicMax key
    if (tid < YCHUNK) {
        float v = FLT_MAX;
#pragma unroll
        for (int i = 0; i < NW; i++)
            v = fminf(v, fminf(scol[i][tid], scol[i][tid + YCHUNK]));
        unsigned int key = ~__float_as_uint(fmaxf(v, 0.0f));
        atomicMax(&g_colkey[(size_t)b * M + yc * YCHUNK + tid], key);
    }
}

// 4 blocks x 1024 threads, one block per batch. Each thread does EXACTLY
// TWO independent uint4 loads (one row segment, one col segment) so all
// memory latency is a single overlapped round (previous version's 8
// dependent rounds were the bottleneck). Resets keys to 0 (identity for
// next replay), sqrt-sums, writes out[b]. Deterministic: fixed
// accumulation and reduction order. PDL secondary.
__global__ __launch_bounds__(1024) void chamfer_reduce(float* __restrict__ out) {
    cudaGridDependencySynchronize();

    int b   = blockIdx.x;
    int tid = threadIdx.x;

    uint4* rbase = (uint4*)(g_rowkey + (size_t)b * M);   // 1024 uint4
    uint4* cbase = (uint4*)(g_colkey + (size_t)b * M);   // 1024 uint4
    const uint4 zero4 = make_uint4(0u, 0u, 0u, 0u);

    // both loads issued back-to-back, independent -> one latency round
    uint4 kr = rbase[tid];
    uint4 kc = cbase[tid];
    rbase[tid] = zero4;
    cbase[tid] = zero4;

    float sum =
        sqrtf(__uint_as_float(~kr.x)) + sqrtf(__uint_as_float(~kr.y)) +
        sqrtf(__uint_as_float(~kr.z)) + sqrtf(__uint_as_float(~kr.w)) +
        sqrtf(__uint_as_float(~kc.x)) + sqrtf(__uint_as_float(~kc.y)) +
        sqrtf(__uint_as_float(~kc.z)) + sqrtf(__uint_as_float(~kc.w));

    __shared__ float red[32];
    for (int o = 16; o; o >>= 1) sum += __shfl_down_sync(0xffffffffu, sum, o);
    if ((tid & 31) == 0) red[tid >> 5] = sum;
    __syncthreads();
    if (tid < 32) {
        float s = red[tid];
        for (int o = 16; o; o >>= 1) s += __shfl_down_sync(0xffffffffu, s, o);
        if (tid == 0) out[b] = s * (1.0f / (float)M);
    }
}

extern "C" void kernel_launch(void* const* d_in, const int* in_sizes, int n_in,
                              void* d_out, int out_size) {
    const float* x = (const float*)d_in[0];
    const float* y = (const float*)d_in[1];
    float* out = (float*)d_out;

    chamfer_main<<<NBLK, TX>>>(x, y);

    cudaLaunchConfig_t cfg = {};
    cfg.gridDim = dim3(BATCH, 1, 1);
    cfg.blockDim = dim3(1024, 1, 1);
    cfg.dynamicSmemBytes = 0;
    cfg.stream = 0;
    cudaLaunchAttribute attr[1];
    attr[0].id = cudaLaunchAttributeProgrammaticStreamSerialization;
    attr[0].val.programmaticStreamSerializationAllowed = 1;
    cfg.attrs = attr;
    cfg.numAttrs = 1;
    cudaLaunchKernelEx(&cfg, chamfer_reduce, out);
}